// round 14
// baseline (speedup 1.0000x reference)
#include <cuda_runtime.h>
#include <cuda_fp16.h>
#include <cstdint>
#include <math.h>

#define NB 8
#define CIN 256
#define HWSZ 16384
#define OCB 256
#define NCLS 18
#define NREG 36
#define NTOT 54
#define BNEPS 1e-5f
#define NT 32768        // total 2x2 output tiles (8 imgs * 64*64)

// ---------------- scratch (device globals) ----------------
__device__ __half sc_V[(size_t)8 * 16 * NT * 32];   // [ch][xi][t][32ci perm+swz]  268MB
__device__ __half sc_U[(size_t)8 * 16 * 256 * 32];  // [ch][xi][oc][32ci perm+swz] 2MB
__device__ float sc_base[(size_t)NB * OCB * HWSZ];  // conv+mish output NCHW
__device__ float sc_part[256][1024][2];             // per-CTA BN partials
__device__ float sc_cls[(size_t)NB * NCLS * HWSZ];
__device__ float sc_reg[(size_t)NB * NREG * HWSZ];
__device__ float sc_scaleA[CIN];
__device__ float sc_shiftA[CIN];
__device__ float sc_Wf[NTOT * CIN];
__device__ float sc_bf[NTOT];
__device__ float sc_s2[NTOT];
__device__ float sc_h2[NTOT];

// ---------------- helpers ----------------
__device__ __forceinline__ uint32_t smem_u32(const void* p) {
    return (uint32_t)__cvta_generic_to_shared(p);
}
__device__ __forceinline__ unsigned long long pk2(float v) {
    unsigned long long r; unsigned u = __float_as_uint(v);
    asm("mov.b64 %0, {%1, %2};" : "=l"(r) : "r"(u), "r"(u));
    return r;
}
__device__ __forceinline__ unsigned long long pk2ab(float a, float b) {
    unsigned long long r;
    asm("mov.b64 %0, {%1, %2};" : "=l"(r) : "r"(__float_as_uint(a)), "r"(__float_as_uint(b)));
    return r;
}
__device__ __forceinline__ void fma2(unsigned long long& d, unsigned long long a, unsigned long long b) {
    asm("fma.rn.f32x2 %0, %1, %2, %0;" : "+l"(d) : "l"(a), "l"(b));
}
__device__ __forceinline__ float2 upk(unsigned long long v) {
    unsigned lo, hi;
    asm("mov.b64 {%0, %1}, %2;" : "=r"(lo), "=r"(hi) : "l"(v));
    return make_float2(__uint_as_float(lo), __uint_as_float(hi));
}
__device__ __forceinline__ float mishf(float v) {
    float sp = fmaxf(v, 0.f) + log1pf(expf(-fabsf(v)));
    return v * tanhf(sp);
}
__device__ __forceinline__ float block_reduce(float v, float* red, int tid) {
    red[tid] = v; __syncthreads();
#pragma unroll
    for (int o = 128; o > 0; o >>= 1) {
        if (tid < o) red[tid] += red[tid + o];
        __syncthreads();
    }
    float r = red[0];
    __syncthreads();
    return r;
}
__device__ __forceinline__ int pidx16(int k) {
    return (k < 8) ? ((k >> 1) * 4 + (k & 1)) : (((k - 8) >> 1) * 4 + 2 + (k & 1));
}
__device__ __forceinline__ int pidx32h(int a) {
    return (a & 16) + pidx16(a & 15);
}
__device__ __forceinline__ int swz(int p) {
    int t = (p >> 1) & 3;
    return t ^ ((t & 1) << 2);
}

#define MBAR_INIT(a, c) \
    asm volatile("mbarrier.init.shared.b64 [%0], %1;" :: "r"((uint32_t)(a)), "r"((uint32_t)(c)) : "memory")
#define MBAR_EXPECT(a, bytes) \
    asm volatile("mbarrier.arrive.expect_tx.shared.b64 _, [%0], %1;" :: "r"((uint32_t)(a)), "r"((uint32_t)(bytes)) : "memory")
#define MBAR_WAIT(a, p) do {                                                         \
    uint32_t _m = (uint32_t)(a), _p = (uint32_t)(p), _d;                             \
    asm volatile("{\n\t.reg .pred q;\n\t"                                            \
        "mbarrier.try_wait.parity.acquire.cta.shared::cta.b64 q, [%1], %2;\n\t"      \
        "selp.b32 %0, 1, 0, q;\n\t}" : "=r"(_d) : "r"(_m), "r"(_p) : "memory");      \
    if (!_d) {                                                                       \
        asm volatile("{\n\t.reg .pred Q;\n\tWL_%=:\n\t"                              \
            "mbarrier.try_wait.parity.acquire.cta.shared::cta.b64 Q, [%0], %1, 0x989680;\n\t" \
            "@Q bra.uni WD_%=;\n\tbra.uni WL_%=;\n\tWD_%=:\n\t}"                     \
            :: "r"(_m), "r"(_p) : "memory");                                         \
    }                                                                                \
} while (0)

__device__ __forceinline__ void bulk_cp(uint32_t dst, const void* src, uint32_t bytes, uint32_t mbar) {
    asm volatile(
        "cp.async.bulk.shared::cluster.global.mbarrier::complete_tx::bytes [%0], [%1], %2, [%3];"
        :: "r"(dst), "l"(src), "r"(bytes), "r"(mbar) : "memory");
}

// ---------------- kU: weight transform G g G^T -> U ----------------
__global__ void kU(const float* __restrict__ W) {
    int oc = blockIdx.x, ci = threadIdx.x;
    const float* g = W + ((size_t)oc * CIN + ci) * 9;
    float t4[4][3];
#pragma unroll
    for (int c = 0; c < 3; c++) {
        float g0 = g[c], g1 = g[3 + c], g2 = g[6 + c];
        t4[0][c] = g0;
        t4[1][c] = 0.5f * (g0 + g1 + g2);
        t4[2][c] = 0.5f * (g0 - g1 + g2);
        t4[3][c] = g2;
    }
    int ch = ci >> 5, p = pidx32h(ci & 31);
    int pos = ((p >> 2) ^ swz(oc & 7)) * 4 + (p & 3);
#pragma unroll
    for (int i = 0; i < 4; i++) {
        float u0 = t4[i][0];
        float u1 = 0.5f * (t4[i][0] + t4[i][1] + t4[i][2]);
        float u2 = 0.5f * (t4[i][0] - t4[i][1] + t4[i][2]);
        float u3 = t4[i][2];
        sc_U[(((size_t)ch * 16 + i * 4 + 0) * 256 + oc) * 32 + pos] = __float2half_rn(u0);
        sc_U[(((size_t)ch * 16 + i * 4 + 1) * 256 + oc) * 32 + pos] = __float2half_rn(u1);
        sc_U[(((size_t)ch * 16 + i * 4 + 2) * 256 + oc) * 32 + pos] = __float2half_rn(u2);
        sc_U[(((size_t)ch * 16 + i * 4 + 3) * 256 + oc) * 32 + pos] = __float2half_rn(u3);
    }
}

// ---------------- kV: input transform B^T d B -> V (reads x NCHW directly) ----------------
#define KV_SMEM (33792 + 32768)
__global__ void kV(const float* __restrict__ x) {
    extern __shared__ float dsm[];
    float* xs = dsm;                      // [ci32][4r][66c]
    __half* vs = (__half*)(dsm + 8448);   // [xi16][t32][32]
    int bx = blockIdx.x;
    int ch = bx >> 1, txs = bx & 1;
    int ty = blockIdx.y, n = blockIdx.z;
    int tid = threadIdx.x;
    int gy0 = 2 * ty - 1, gx0 = txs * 64 - 1;
    for (int i = tid; i < 8448; i += 256) {
        int ci = i / 264, rm = i - ci * 264;
        int r = rm / 66, cc = rm - r * 66;
        int gy = gy0 + r, gx = gx0 + cc;
        float v = 0.f;
        if ((unsigned)gy < 128u && (unsigned)gx < 128u)
            v = x[((size_t)(n * CIN + ch * 32 + ci)) * HWSZ + gy * 128 + gx];
        xs[i] = v;
    }
    __syncthreads();
#pragma unroll
    for (int u = 0; u < 4; u++) {
        int pr = tid + u * 256;
        int tx = pr & 31, ci = pr >> 5;
        const float* bp = xs + ci * 264 + 2 * tx;
        float d[4][4];
#pragma unroll
        for (int r = 0; r < 4; r++)
#pragma unroll
            for (int c = 0; c < 4; c++) d[r][c] = bp[r * 66 + c];
        float t4[4][4];
#pragma unroll
        for (int c = 0; c < 4; c++) {
            t4[0][c] = d[0][c] - d[2][c];
            t4[1][c] = d[1][c] + d[2][c];
            t4[2][c] = d[2][c] - d[1][c];
            t4[3][c] = d[1][c] - d[3][c];
        }
        int p = pidx32h(ci);
        int pos = ((p >> 2) ^ swz(tx & 7)) * 4 + (p & 3);
#pragma unroll
        for (int i2 = 0; i2 < 4; i2++) {
            vs[((i2 * 4 + 0) * 32 + tx) * 32 + pos] = __float2half_rn(t4[i2][0] - t4[i2][2]);
            vs[((i2 * 4 + 1) * 32 + tx) * 32 + pos] = __float2half_rn(t4[i2][1] + t4[i2][2]);
            vs[((i2 * 4 + 2) * 32 + tx) * 32 + pos] = __float2half_rn(t4[i2][2] - t4[i2][1]);
            vs[((i2 * 4 + 3) * 32 + tx) * 32 + pos] = __float2half_rn(t4[i2][1] - t4[i2][3]);
        }
    }
    __syncthreads();
    int tg0 = n * 4096 + ty * 64 + txs * 32;
    const uint4* sv = (const uint4*)vs;
    for (int i = tid; i < 2048; i += 256) {
        int xi = i >> 7, rest = i & 127;
        *((uint4*)(sc_V + (((size_t)ch * 16 + xi) * NT + tg0) * 32) + rest) = sv[i];
    }
}

// ---------------- kG: 16 xi-GEMMs + fused output transform ----------------
// CTA 256 thr / 8 warps; warp j owns xi {j, 8+j}; tile M=32 tiles x N=64 oc.
// Stage (16 = 8 ci-chunks x 2 xi-groups): A 8xi*32t*32 (16KB) + B 8xi*64oc*32 (32KB)
#define GST_H 24576
#define GST_B 49152u
#define G_SMEM (98304 + 32)

__device__ __forceinline__ void g_issue(int ch, int g, int t0, int oc0,
                                        uint32_t smbase, int buf, uint32_t mbar) {
    MBAR_EXPECT(mbar, GST_B);
    uint32_t dst = smbase + (uint32_t)buf * GST_B;
#pragma unroll
    for (int q = 0; q < 8; q++) {
        int xi = g * 8 + q;
        bulk_cp(dst + q * 2048u, sc_V + (((size_t)ch * 16 + xi) * NT + t0) * 32, 2048u, mbar);
        bulk_cp(dst + 16384u + q * 4096u,
                sc_U + (((size_t)ch * 16 + xi) * 256 + oc0) * 32, 4096u, mbar);
    }
}

__device__ __forceinline__ void g_compute(const __half* A, const __half* Bp,
                                          float (&acc)[2][8][4], int mrow, int kc, int xsw) {
#pragma unroll
    for (int ks = 0; ks < 2; ks++) {
        int e = ((ks * 4 + kc) ^ xsw) * 4;
        uint32_t af[2][4];
#pragma unroll
        for (int mf = 0; mf < 2; mf++) {
            const __half* pa = A + (mf * 16 + mrow) * 32 + e;
            uint2 lo = *(const uint2*)pa;
            uint2 hi = *(const uint2*)(pa + 256);
            af[mf][0] = lo.x; af[mf][1] = hi.x; af[mf][2] = lo.y; af[mf][3] = hi.y;
        }
#pragma unroll
        for (int nf = 0; nf < 8; nf++) {
            uint2 bv = *(const uint2*)(Bp + (nf * 8 + mrow) * 32 + e);
#pragma unroll
            for (int mf = 0; mf < 2; mf++)
                asm volatile(
                    "mma.sync.aligned.m16n8k16.row.col.f32.f16.f16.f32 "
                    "{%0,%1,%2,%3}, {%4,%5,%6,%7}, {%8,%9}, {%0,%1,%2,%3};"
                    : "+f"(acc[mf][nf][0]), "+f"(acc[mf][nf][1]),
                      "+f"(acc[mf][nf][2]), "+f"(acc[mf][nf][3])
                    : "r"(af[mf][0]), "r"(af[mf][1]), "r"(af[mf][2]), "r"(af[mf][3]),
                      "r"(bv.x), "r"(bv.y));
        }
    }
}

__global__ void __launch_bounds__(256, 1) kG(const float* __restrict__ pb) {
    extern __shared__ __half smh[];
    uint32_t smbase = smem_u32(smh);
    int tid = threadIdx.x, lane = tid & 31, wid = tid >> 5;
    int ocb = blockIdx.x, tblk = blockIdx.y;
    int t0 = tblk * 32, oc0 = ocb * 64;
    int mrow = lane >> 2, kc = lane & 3, xsw = swz(mrow);

    float acc0[2][8][4], acc1[2][8][4];
#pragma unroll
    for (int a = 0; a < 2; a++)
#pragma unroll
        for (int b = 0; b < 8; b++)
#pragma unroll
            for (int c = 0; c < 4; c++) { acc0[a][b][c] = 0.f; acc1[a][b][c] = 0.f; }

    uint32_t mb0 = smbase + 98304u, mb1 = mb0 + 8;
    if (tid == 0) { MBAR_INIT(mb0, 1); MBAR_INIT(mb1, 1); }
    __syncthreads();
    if (tid == 0) {
        g_issue(0, 0, t0, oc0, smbase, 0, mb0);
        g_issue(0, 1, t0, oc0, smbase, 1, mb1);
    }

#pragma unroll 1
    for (int st = 0; st < 16; st++) {
        MBAR_WAIT(st & 1 ? mb1 : mb0, (st >> 1) & 1);
        const __half* A = smh + (st & 1) * GST_H + wid * 1024;
        const __half* Bp = smh + (st & 1) * GST_H + 8192 + wid * 2048;
        if (st & 1) g_compute(A, Bp, acc1, mrow, kc, xsw);
        else g_compute(A, Bp, acc0, mrow, kc, xsw);
        __syncthreads();
        if (st + 2 < 16 && tid == 0)
            g_issue((st + 2) >> 1, (st + 2) & 1, t0, oc0, smbase, st & 1, st & 1 ? mb1 : mb0);
    }

    // ---- fused epilogue: A^T M A + bias + mish + NCHW store + BN partials ----
    float* Ms = (float*)smh;          // [16xi][32t][8oc]
    float* ps = (float*)smh + 4096;   // [8r][32t][8oc][2]
    int nimg = t0 >> 12, rem = t0 & 4095;
    int ty2 = ((rem >> 6)) * 2, tx0 = rem & 63;
    int tl = tid >> 3, ocl = tid & 7;
#pragma unroll
    for (int r = 0; r < 8; r++) {
        __syncthreads();
#pragma unroll
        for (int mf = 0; mf < 2; mf++) {
            float* q0 = &Ms[((wid) * 32 + mf * 16 + mrow) * 8 + 2 * kc];
            q0[0] = acc0[mf][r][0]; q0[1] = acc0[mf][r][1];
            q0[64] = acc0[mf][r][2]; q0[65] = acc0[mf][r][3];
            float* q1 = &Ms[((8 + wid) * 32 + mf * 16 + mrow) * 8 + 2 * kc];
            q1[0] = acc1[mf][r][0]; q1[1] = acc1[mf][r][1];
            q1[64] = acc1[mf][r][2]; q1[65] = acc1[mf][r][3];
        }
        __syncthreads();
        float m[16];
#pragma unroll
        for (int xi = 0; xi < 16; xi++) m[xi] = Ms[(xi * 32 + tl) * 8 + ocl];
        float ta[2][4];
#pragma unroll
        for (int c = 0; c < 4; c++) {
            ta[0][c] = m[c] + m[4 + c] + m[8 + c];
            ta[1][c] = m[4 + c] - m[8 + c] - m[12 + c];
        }
        int oc = oc0 + r * 8 + ocl;
        float bv = pb[oc];
        float o00 = mishf(ta[0][0] + ta[0][1] + ta[0][2] + bv);
        float o01 = mishf(ta[0][1] - ta[0][2] - ta[0][3] + bv);
        float o10 = mishf(ta[1][0] + ta[1][1] + ta[1][2] + bv);
        float o11 = mishf(ta[1][1] - ta[1][2] - ta[1][3] + bv);
        float* op = sc_base + ((size_t)(nimg * OCB + oc)) * HWSZ + ty2 * 128 + (tx0 + tl) * 2;
        op[0] = o00; op[1] = o01; op[128] = o10; op[129] = o11;
        ps[((r * 32 + tl) * 8 + ocl) * 2 + 0] = o00 + o01 + o10 + o11;
        ps[((r * 32 + tl) * 8 + ocl) * 2 + 1] = o00 * o00 + o01 * o01 + o10 * o10 + o11 * o11;
    }
    __syncthreads();
    if (tid < 128) {
        int r = tid >> 4, oz = (tid >> 1) & 7, v = tid & 1;
        float s = 0.f;
        for (int t = 0; t < 32; t++) s += ps[((r * 32 + t) * 8 + oz) * 2 + v];
        sc_part[oc0 + r * 8 + oz][tblk][v] = s;
    }
}

// ---------------- K2: base BN stats from 1024 partials ----------------
__global__ void k2_base_stats(const float* __restrict__ gam, const float* __restrict__ bet) {
    __shared__ float red[256];
    int c = blockIdx.x, tid = threadIdx.x;
    float s = 0.f, q = 0.f;
    for (int i = tid; i < 1024; i += 256) { s += sc_part[c][i][0]; q += sc_part[c][i][1]; }
    float sum = block_reduce(s, red, tid);
    float sq = block_reduce(q, red, tid);
    if (tid == 0) {
        float inv_n = 1.f / (float)(NB * HWSZ);
        float mean = sum * inv_n;
        float var = sq * inv_n - mean * mean;
        float inv = rsqrtf(var + BNEPS);
        float scl = gam[c] * inv;
        sc_scaleA[c] = scl;
        sc_shiftA[c] = bet[c] - mean * scl;
    }
}

// ---------------- K3: fold base BN into 1x1 conv weights ----------------
__global__ void k3_fold(const float* __restrict__ Wc, const float* __restrict__ bc,
                        const float* __restrict__ Wr, const float* __restrict__ br) {
    __shared__ float red[256];
    int o = blockIdx.x, ci = threadIdx.x;
    const float* Ws;
    float bs;
    int ol;
    if (o < NCLS) { Ws = Wc; ol = o; bs = bc[o]; }
    else { Ws = Wr; ol = o - NCLS; bs = br[ol]; }
    float w = Ws[ol * CIN + ci];
    sc_Wf[o * CIN + ci] = w * sc_scaleA[ci];
    float tot = block_reduce(w * sc_shiftA[ci], red, ci);
    if (ci == 0) sc_bf[o] = bs + tot;
}

// ---------------- K4m: merged 1x1 convs (cls+reg) ----------------
#define K4_SMEM (CIN * 56 * 4)
__global__ void __launch_bounds__(256) k4m() {
    extern __shared__ float swf[];
    int tid = threadIdx.x;
    for (int i = tid; i < CIN * 56; i += 256) {
        int c = i / 56, o = i - c * 56;
        swf[i] = (o < NTOT) ? sc_Wf[o * CIN + c] : 0.f;
    }
    __syncthreads();
    int pstart = blockIdx.x * 512;
    int n = pstart >> 14;
    int hwb = (pstart & 16383) + tid;

    unsigned long long acc2[27][2];
#pragma unroll
    for (int op = 0; op < 27; op++) {
        unsigned long long b = pk2ab(sc_bf[2 * op], sc_bf[2 * op + 1]);
        acc2[op][0] = b;
        acc2[op][1] = b;
    }
    const float* bpn = sc_base + (size_t)n * OCB * HWSZ + hwb;
#pragma unroll 1
    for (int c = 0; c < CIN; c += 8) {
        float v0[8], v1[8];
#pragma unroll
        for (int u = 0; u < 8; u++) {
            const float* p = bpn + (size_t)(c + u) * HWSZ;
            v0[u] = p[0];
            v1[u] = p[256];
        }
#pragma unroll
        for (int u = 0; u < 8; u++) {
            unsigned long long p0 = pk2(v0[u]), p1 = pk2(v1[u]);
            const unsigned long long* wrow = (const unsigned long long*)(swf + (c + u) * 56);
#pragma unroll
            for (int op = 0; op < 27; op++) {
                unsigned long long w = wrow[op];
                fma2(acc2[op][0], w, p0);
                fma2(acc2[op][1], w, p1);
            }
        }
    }
#pragma unroll
    for (int op = 0; op < 27; op++)
#pragma unroll
        for (int px = 0; px < 2; px++) {
            float2 u = upk(acc2[op][px]);
            int ch0 = 2 * op, ch1 = 2 * op + 1;
            size_t idx = hwb + px * 256;
            if (ch0 < NCLS) sc_cls[(size_t)(n * NCLS + ch0) * HWSZ + idx] = u.x;
            else sc_reg[(size_t)(n * NREG + (ch0 - NCLS)) * HWSZ + idx] = u.x;
            if (ch1 < NCLS) sc_cls[(size_t)(n * NCLS + ch1) * HWSZ + idx] = u.y;
            else sc_reg[(size_t)(n * NREG + (ch1 - NCLS)) * HWSZ + idx] = u.y;
        }
}

// ---------------- K5: cls/reg BN stats ----------------
__global__ void k5_stats2(const float* __restrict__ gc, const float* __restrict__ bc,
                          const float* __restrict__ gr, const float* __restrict__ br) {
    __shared__ float red[256];
    int b = blockIdx.x, tid = threadIdx.x;
    const float* src;
    int nch, ch;
    float gam, bet;
    if (b < NCLS) { src = sc_cls; nch = NCLS; ch = b; gam = gc[ch]; bet = bc[ch]; }
    else { src = sc_reg; nch = NREG; ch = b - NCLS; gam = gr[ch]; bet = br[ch]; }
    float s = 0.f;
    for (int n = 0; n < NB; n++) {
        const float* p = &src[(size_t)(n * nch + ch) * HWSZ];
        for (int i = tid; i < HWSZ; i += 256) s += p[i];
    }
    float mean = block_reduce(s, red, tid) * (1.f / (NB * HWSZ));
    s = 0.f;
    for (int n = 0; n < NB; n++) {
        const float* p = &src[(size_t)(n * nch + ch) * HWSZ];
        for (int i = tid; i < HWSZ; i += 256) {
            float d = p[i] - mean;
            s += d * d;
        }
    }
    float var = block_reduce(s, red, tid) * (1.f / (NB * HWSZ));
    if (tid == 0) {
        float inv = rsqrtf(var + BNEPS);
        float scl = gam * inv;
        sc_s2[b] = scl;
        sc_h2[b] = bet - mean * scl;
    }
}

// ---------------- K6: softmax + anchor decode ----------------
__constant__ float c_wa[9] = {455.f, 911.f, 1823.f, 319.f, 639.f, 1279.f, 223.f, 447.f, 895.f};
__constant__ float c_ha[9] = {223.f, 447.f, 895.f, 319.f, 639.f, 1279.f, 447.f, 895.f, 1791.f};

__global__ void k6_decode(const int* __restrict__ imgsz, float* __restrict__ out) {
    int t = blockIdx.x * 256 + threadIdx.x;
    if (t >= NB * HWSZ) return;
    int n = t >> 14, hw = t & 16383;
    int hy = hw >> 7, wx = hw & 127;
    float lim = 2048.f;
    if (imgsz) {
        int iv = *imgsz;
        lim = (iv > 0 && iv < (1 << 24)) ? (float)iv : __int_as_float(iv);
    }
    float cls[NCLS], rg[NREG];
#pragma unroll
    for (int o = 0; o < NCLS; o++)
        cls[o] = sc_cls[(size_t)(n * NCLS + o) * HWSZ + hw] * sc_s2[o] + sc_h2[o];
#pragma unroll
    for (int o = 0; o < NREG; o++)
        rg[o] = sc_reg[(size_t)(n * NREG + o) * HWSZ + hw] * sc_s2[NCLS + o] + sc_h2[NCLS + o];

    const size_t K = (size_t)HWSZ * 9;
    float* fg = out;
    float* ts = out + (size_t)NB * K;
    float* ro = ts + (size_t)NB * K * 4;
    size_t kb = (size_t)n * K + (size_t)hw * 9;

    float cxa = 19.5f + 16.f * (float)wx;
    float cya = 19.5f + 16.f * (float)hy;
#pragma unroll
    for (int a = 0; a < 9; a++) {
        float wa = c_wa[a], ha = c_ha[a];
        float x1 = fminf(fmaxf(rg[a * 4 + 0] + (cxa - 0.5f * wa), 0.f), lim);
        float y1 = fminf(fmaxf(rg[a * 4 + 1] + (cya - 0.5f * ha), 0.f), lim);
        float x2 = fminf(fmaxf(rg[a * 4 + 2] + (cxa + 0.5f * wa), 0.f), lim);
        float y2 = fminf(fmaxf(rg[a * 4 + 3] + (cya + 0.5f * ha), 0.f), lim);
        float w = x2 - x1, h = y2 - y1;
        float cx = x1 + 0.5f * w, cy = y1 + 0.5f * h;
        float s0 = cls[a * 2], s1 = cls[a * 2 + 1];
        fg[kb + a] = 1.f / (1.f + expf(s0 - s1));
        size_t o4 = (kb + a) * 4;
        ts[o4 + 0] = (cx - cxa) / wa;
        ts[o4 + 1] = (cy - cya) / ha;
        ts[o4 + 2] = logf(fmaxf(w / wa, 1e-30f));
        ts[o4 + 3] = logf(fmaxf(h / ha, 1e-30f));
        ro[o4 + 0] = cx;
        ro[o4 + 1] = cy;
        ro[o4 + 2] = w;
        ro[o4 + 3] = h;
    }
}

// ---------------- launch ----------------
extern "C" void kernel_launch(void* const* d_in, const int* in_sizes, int n_in,
                              void* d_out, int out_size) {
    const float* x   = (const float*)d_in[0];
    const float* Wb  = (const float*)d_in[1];
    const float* bb  = (const float*)d_in[2];
    const float* gb  = (const float*)d_in[3];
    const float* beb = (const float*)d_in[4];
    const float* Wc  = (const float*)d_in[5];
    const float* bc  = (const float*)d_in[6];
    const float* gc  = (const float*)d_in[7];
    const float* bec = (const float*)d_in[8];
    const float* Wr  = (const float*)d_in[9];
    const float* br  = (const float*)d_in[10];
    const float* gr  = (const float*)d_in[11];
    const float* ber = (const float*)d_in[12];
    const int* imgsz = (n_in > 13) ? (const int*)d_in[13] : nullptr;
    float* out = (float*)d_out;

    static int smem_set = 0;
    if (!smem_set) {
        cudaFuncSetAttribute(kG, cudaFuncAttributeMaxDynamicSharedMemorySize, G_SMEM);
        cudaFuncSetAttribute(kV, cudaFuncAttributeMaxDynamicSharedMemorySize, KV_SMEM);
        cudaFuncSetAttribute(k4m, cudaFuncAttributeMaxDynamicSharedMemorySize, K4_SMEM);
        smem_set = 1;
    }

    kU<<<256, 256>>>(Wb);
    kV<<<dim3(16, 64, NB), 256, KV_SMEM>>>(x);
    kG<<<dim3(4, 1024), 256, G_SMEM>>>(bb);

    k2_base_stats<<<OCB, 256>>>(gb, beb);
    k3_fold<<<NTOT, 256>>>(Wc, bc, Wr, br);
    k4m<<<NB * HWSZ / 512, 256, K4_SMEM>>>();
    k5_stats2<<<NTOT, 256>>>(gc, bec, gr, ber);
    k6_decode<<<NB * HWSZ / 256, 256>>>(imgsz, out);
}

// round 15
// speedup vs baseline: 1.0006x; 1.0006x over previous
#include <cuda_runtime.h>
#include <cuda_fp16.h>
#include <cstdint>
#include <math.h>

#define NB 8
#define CIN 256
#define HWSZ 16384
#define OCB 256
#define NCLS 18
#define NREG 36
#define NTOT 54
#define BNEPS 1e-5f
#define NT 32768        // total 2x2 output tiles (8 imgs * 64*64)

// ---------------- scratch (device globals) ----------------
__device__ __half sc_V[(size_t)8 * 16 * NT * 32];   // [ch][xi][t][32ci perm+swz]  268MB
__device__ __half sc_U[(size_t)8 * 16 * 256 * 32];  // [ch][xi][oc][32ci perm+swz] 2MB
__device__ __half sc_base[(size_t)NB * OCB * HWSZ]; // conv+mish output NCHW (fp16)
__device__ float sc_part[256][1024][2];             // per-CTA BN partials
__device__ float sc_cls[(size_t)NB * NCLS * HWSZ];
__device__ float sc_reg[(size_t)NB * NREG * HWSZ];
__device__ float sc_scaleA[CIN];
__device__ float sc_shiftA[CIN];
__device__ float sc_Wf[NTOT * CIN];
__device__ float sc_bf[NTOT];
__device__ float sc_s2[NTOT];
__device__ float sc_h2[NTOT];

// ---------------- helpers ----------------
__device__ __forceinline__ uint32_t smem_u32(const void* p) {
    return (uint32_t)__cvta_generic_to_shared(p);
}
__device__ __forceinline__ unsigned long long pk2(float v) {
    unsigned long long r; unsigned u = __float_as_uint(v);
    asm("mov.b64 %0, {%1, %2};" : "=l"(r) : "r"(u), "r"(u));
    return r;
}
__device__ __forceinline__ unsigned long long pk2ab(float a, float b) {
    unsigned long long r;
    asm("mov.b64 %0, {%1, %2};" : "=l"(r) : "r"(__float_as_uint(a)), "r"(__float_as_uint(b)));
    return r;
}
__device__ __forceinline__ void fma2(unsigned long long& d, unsigned long long a, unsigned long long b) {
    asm("fma.rn.f32x2 %0, %1, %2, %0;" : "+l"(d) : "l"(a), "l"(b));
}
__device__ __forceinline__ float2 upk(unsigned long long v) {
    unsigned lo, hi;
    asm("mov.b64 {%0, %1}, %2;" : "=r"(lo), "=r"(hi) : "l"(v));
    return make_float2(__uint_as_float(lo), __uint_as_float(hi));
}
__device__ __forceinline__ float mishf(float v) {
    float sp = fmaxf(v, 0.f) + log1pf(expf(-fabsf(v)));
    return v * tanhf(sp);
}
__device__ __forceinline__ float block_reduce(float v, float* red, int tid) {
    red[tid] = v; __syncthreads();
#pragma unroll
    for (int o = 128; o > 0; o >>= 1) {
        if (tid < o) red[tid] += red[tid + o];
        __syncthreads();
    }
    float r = red[0];
    __syncthreads();
    return r;
}
__device__ __forceinline__ int pidx16(int k) {
    return (k < 8) ? ((k >> 1) * 4 + (k & 1)) : (((k - 8) >> 1) * 4 + 2 + (k & 1));
}
__device__ __forceinline__ int pidx32h(int a) {
    return (a & 16) + pidx16(a & 15);
}
__device__ __forceinline__ int swz(int p) {
    int t = (p >> 1) & 3;
    return t ^ ((t & 1) << 2);
}

#define MBAR_INIT(a, c) \
    asm volatile("mbarrier.init.shared.b64 [%0], %1;" :: "r"((uint32_t)(a)), "r"((uint32_t)(c)) : "memory")
#define MBAR_EXPECT(a, bytes) \
    asm volatile("mbarrier.arrive.expect_tx.shared.b64 _, [%0], %1;" :: "r"((uint32_t)(a)), "r"((uint32_t)(bytes)) : "memory")
#define MBAR_WAIT(a, p) do {                                                         \
    uint32_t _m = (uint32_t)(a), _p = (uint32_t)(p), _d;                             \
    asm volatile("{\n\t.reg .pred q;\n\t"                                            \
        "mbarrier.try_wait.parity.acquire.cta.shared::cta.b64 q, [%1], %2;\n\t"      \
        "selp.b32 %0, 1, 0, q;\n\t}" : "=r"(_d) : "r"(_m), "r"(_p) : "memory");      \
    if (!_d) {                                                                       \
        asm volatile("{\n\t.reg .pred Q;\n\tWL_%=:\n\t"                              \
            "mbarrier.try_wait.parity.acquire.cta.shared::cta.b64 Q, [%0], %1, 0x989680;\n\t" \
            "@Q bra.uni WD_%=;\n\tbra.uni WL_%=;\n\tWD_%=:\n\t}"                     \
            :: "r"(_m), "r"(_p) : "memory");                                         \
    }                                                                                \
} while (0)

__device__ __forceinline__ void bulk_cp(uint32_t dst, const void* src, uint32_t bytes, uint32_t mbar) {
    asm volatile(
        "cp.async.bulk.shared::cluster.global.mbarrier::complete_tx::bytes [%0], [%1], %2, [%3];"
        :: "r"(dst), "l"(src), "r"(bytes), "r"(mbar) : "memory");
}

// ---------------- kdummy: profiling alignment no-op ----------------
__global__ void kdummy() {}

// ---------------- kU: weight transform G g G^T -> U ----------------
__global__ void kU(const float* __restrict__ W) {
    int oc = blockIdx.x, ci = threadIdx.x;
    const float* g = W + ((size_t)oc * CIN + ci) * 9;
    float t4[4][3];
#pragma unroll
    for (int c = 0; c < 3; c++) {
        float g0 = g[c], g1 = g[3 + c], g2 = g[6 + c];
        t4[0][c] = g0;
        t4[1][c] = 0.5f * (g0 + g1 + g2);
        t4[2][c] = 0.5f * (g0 - g1 + g2);
        t4[3][c] = g2;
    }
    int ch = ci >> 5, p = pidx32h(ci & 31);
    int pos = ((p >> 2) ^ swz(oc & 7)) * 4 + (p & 3);
#pragma unroll
    for (int i = 0; i < 4; i++) {
        float u0 = t4[i][0];
        float u1 = 0.5f * (t4[i][0] + t4[i][1] + t4[i][2]);
        float u2 = 0.5f * (t4[i][0] - t4[i][1] + t4[i][2]);
        float u3 = t4[i][2];
        sc_U[(((size_t)ch * 16 + i * 4 + 0) * 256 + oc) * 32 + pos] = __float2half_rn(u0);
        sc_U[(((size_t)ch * 16 + i * 4 + 1) * 256 + oc) * 32 + pos] = __float2half_rn(u1);
        sc_U[(((size_t)ch * 16 + i * 4 + 2) * 256 + oc) * 32 + pos] = __float2half_rn(u2);
        sc_U[(((size_t)ch * 16 + i * 4 + 3) * 256 + oc) * 32 + pos] = __float2half_rn(u3);
    }
}

// ---------------- kV: input transform B^T d B -> V ----------------
// vs rows padded to 36 halves (72B): STS bank conflicts 16-way -> 2-way.
#define KV_SMEM (33792 + 36864)
__global__ void kV(const float* __restrict__ x) {
    extern __shared__ float dsm[];
    float* xs = dsm;                      // [ci32][4r][66c]
    __half* vs = (__half*)(dsm + 8448);   // [xi16][t32][36 pad]
    int bx = blockIdx.x;
    int ch = bx >> 1, txs = bx & 1;
    int ty = blockIdx.y, n = blockIdx.z;
    int tid = threadIdx.x;
    int gy0 = 2 * ty - 1, gx0 = txs * 64 - 1;
    for (int i = tid; i < 8448; i += 256) {
        int ci = i / 264, rm = i - ci * 264;
        int r = rm / 66, cc = rm - r * 66;
        int gy = gy0 + r, gx = gx0 + cc;
        float v = 0.f;
        if ((unsigned)gy < 128u && (unsigned)gx < 128u)
            v = x[((size_t)(n * CIN + ch * 32 + ci)) * HWSZ + gy * 128 + gx];
        xs[i] = v;
    }
    __syncthreads();
#pragma unroll
    for (int u = 0; u < 4; u++) {
        int pr = tid + u * 256;
        int tx = pr & 31, ci = pr >> 5;
        const float* bp = xs + ci * 264 + 2 * tx;
        float d[4][4];
#pragma unroll
        for (int r = 0; r < 4; r++)
#pragma unroll
            for (int c = 0; c < 4; c++) d[r][c] = bp[r * 66 + c];
        float t4[4][4];
#pragma unroll
        for (int c = 0; c < 4; c++) {
            t4[0][c] = d[0][c] - d[2][c];
            t4[1][c] = d[1][c] + d[2][c];
            t4[2][c] = d[2][c] - d[1][c];
            t4[3][c] = d[1][c] - d[3][c];
        }
        int p = pidx32h(ci);
        int pos = ((p >> 2) ^ swz(tx & 7)) * 4 + (p & 3);
#pragma unroll
        for (int i2 = 0; i2 < 4; i2++) {
            vs[((i2 * 4 + 0) * 32 + tx) * 36 + pos] = __float2half_rn(t4[i2][0] - t4[i2][2]);
            vs[((i2 * 4 + 1) * 32 + tx) * 36 + pos] = __float2half_rn(t4[i2][1] + t4[i2][2]);
            vs[((i2 * 4 + 2) * 32 + tx) * 36 + pos] = __float2half_rn(t4[i2][2] - t4[i2][1]);
            vs[((i2 * 4 + 3) * 32 + tx) * 36 + pos] = __float2half_rn(t4[i2][1] - t4[i2][3]);
        }
    }
    __syncthreads();
    int tg0 = n * 4096 + ty * 64 + txs * 32;
    for (int i = tid; i < 4096; i += 256) {
        int xi = i >> 8, rem = i & 255, t = rem >> 3, q = rem & 7;
        uint2 val = *(const uint2*)((const char*)vs + (xi * 32 + t) * 72 + q * 8);
        *((uint2*)(sc_V + (((size_t)ch * 16 + xi) * NT + tg0 + t) * 32) + q) = val;
    }
}

// ---------------- kG: 16 xi-GEMMs + fused output transform ----------------
#define GST_H 24576
#define GST_B 49152u
#define G_SMEM (98304 + 32)

__device__ __forceinline__ void g_issue(int ch, int g, int t0, int oc0,
                                        uint32_t smbase, int buf, uint32_t mbar) {
    MBAR_EXPECT(mbar, GST_B);
    uint32_t dst = smbase + (uint32_t)buf * GST_B;
#pragma unroll
    for (int q = 0; q < 8; q++) {
        int xi = g * 8 + q;
        bulk_cp(dst + q * 2048u, sc_V + (((size_t)ch * 16 + xi) * NT + t0) * 32, 2048u, mbar);
        bulk_cp(dst + 16384u + q * 4096u,
                sc_U + (((size_t)ch * 16 + xi) * 256 + oc0) * 32, 4096u, mbar);
    }
}

__device__ __forceinline__ void g_compute(const __half* A, const __half* Bp,
                                          float (&acc)[2][8][4], int mrow, int kc, int xsw) {
#pragma unroll
    for (int ks = 0; ks < 2; ks++) {
        int e = ((ks * 4 + kc) ^ xsw) * 4;
        uint32_t af[2][4];
#pragma unroll
        for (int mf = 0; mf < 2; mf++) {
            const __half* pa = A + (mf * 16 + mrow) * 32 + e;
            uint2 lo = *(const uint2*)pa;
            uint2 hi = *(const uint2*)(pa + 256);
            af[mf][0] = lo.x; af[mf][1] = hi.x; af[mf][2] = lo.y; af[mf][3] = hi.y;
        }
#pragma unroll
        for (int nf = 0; nf < 8; nf++) {
            uint2 bv = *(const uint2*)(Bp + (nf * 8 + mrow) * 32 + e);
#pragma unroll
            for (int mf = 0; mf < 2; mf++)
                asm volatile(
                    "mma.sync.aligned.m16n8k16.row.col.f32.f16.f16.f32 "
                    "{%0,%1,%2,%3}, {%4,%5,%6,%7}, {%8,%9}, {%0,%1,%2,%3};"
                    : "+f"(acc[mf][nf][0]), "+f"(acc[mf][nf][1]),
                      "+f"(acc[mf][nf][2]), "+f"(acc[mf][nf][3])
                    : "r"(af[mf][0]), "r"(af[mf][1]), "r"(af[mf][2]), "r"(af[mf][3]),
                      "r"(bv.x), "r"(bv.y));
        }
    }
}

__global__ void __launch_bounds__(256, 1) kG(const float* __restrict__ pb) {
    extern __shared__ __half smh[];
    uint32_t smbase = smem_u32(smh);
    int tid = threadIdx.x, lane = tid & 31, wid = tid >> 5;
    int ocb = blockIdx.x, tblk = blockIdx.y;
    int t0 = tblk * 32, oc0 = ocb * 64;
    int mrow = lane >> 2, kc = lane & 3, xsw = swz(mrow);

    float acc0[2][8][4], acc1[2][8][4];
#pragma unroll
    for (int a = 0; a < 2; a++)
#pragma unroll
        for (int b = 0; b < 8; b++)
#pragma unroll
            for (int c = 0; c < 4; c++) { acc0[a][b][c] = 0.f; acc1[a][b][c] = 0.f; }

    uint32_t mb0 = smbase + 98304u, mb1 = mb0 + 8;
    if (tid == 0) { MBAR_INIT(mb0, 1); MBAR_INIT(mb1, 1); }
    __syncthreads();
    if (tid == 0) {
        g_issue(0, 0, t0, oc0, smbase, 0, mb0);
        g_issue(0, 1, t0, oc0, smbase, 1, mb1);
    }

#pragma unroll 1
    for (int st = 0; st < 16; st++) {
        MBAR_WAIT(st & 1 ? mb1 : mb0, (st >> 1) & 1);
        const __half* A = smh + (st & 1) * GST_H + wid * 1024;
        const __half* Bp = smh + (st & 1) * GST_H + 8192 + wid * 2048;
        if (st & 1) g_compute(A, Bp, acc1, mrow, kc, xsw);
        else g_compute(A, Bp, acc0, mrow, kc, xsw);
        __syncthreads();
        if (st + 2 < 16 && tid == 0)
            g_issue((st + 2) >> 1, (st + 2) & 1, t0, oc0, smbase, st & 1, st & 1 ? mb1 : mb0);
    }

    // ---- fused epilogue: A^T M A + bias + mish + fp16 NCHW store + BN partials ----
    float* Ms = (float*)smh;          // [16xi][32t][8oc]
    float* ps = (float*)smh + 4096;   // [8r][32t][8oc][2]
    int nimg = t0 >> 12, rem = t0 & 4095;
    int ty2 = ((rem >> 6)) * 2, tx0 = rem & 63;
    int tl = tid >> 3, ocl = tid & 7;
#pragma unroll
    for (int r = 0; r < 8; r++) {
        __syncthreads();
#pragma unroll
        for (int mf = 0; mf < 2; mf++) {
            float* q0 = &Ms[((wid) * 32 + mf * 16 + mrow) * 8 + 2 * kc];
            q0[0] = acc0[mf][r][0]; q0[1] = acc0[mf][r][1];
            q0[64] = acc0[mf][r][2]; q0[65] = acc0[mf][r][3];
            float* q1 = &Ms[((8 + wid) * 32 + mf * 16 + mrow) * 8 + 2 * kc];
            q1[0] = acc1[mf][r][0]; q1[1] = acc1[mf][r][1];
            q1[64] = acc1[mf][r][2]; q1[65] = acc1[mf][r][3];
        }
        __syncthreads();
        float m[16];
#pragma unroll
        for (int xi = 0; xi < 16; xi++) m[xi] = Ms[(xi * 32 + tl) * 8 + ocl];
        float ta[2][4];
#pragma unroll
        for (int c = 0; c < 4; c++) {
            ta[0][c] = m[c] + m[4 + c] + m[8 + c];
            ta[1][c] = m[4 + c] - m[8 + c] - m[12 + c];
        }
        int oc = oc0 + r * 8 + ocl;
        float bv = pb[oc];
        float o00 = mishf(ta[0][0] + ta[0][1] + ta[0][2] + bv);
        float o01 = mishf(ta[0][1] - ta[0][2] - ta[0][3] + bv);
        float o10 = mishf(ta[1][0] + ta[1][1] + ta[1][2] + bv);
        float o11 = mishf(ta[1][1] - ta[1][2] - ta[1][3] + bv);
        __half* op = sc_base + ((size_t)(nimg * OCB + oc)) * HWSZ + ty2 * 128 + (tx0 + tl) * 2;
        *(__half2*)op = __floats2half2_rn(o00, o01);
        *(__half2*)(op + 128) = __floats2half2_rn(o10, o11);
        ps[((r * 32 + tl) * 8 + ocl) * 2 + 0] = o00 + o01 + o10 + o11;
        ps[((r * 32 + tl) * 8 + ocl) * 2 + 1] = o00 * o00 + o01 * o01 + o10 * o10 + o11 * o11;
    }
    __syncthreads();
    if (tid < 128) {
        int r = tid >> 4, oz = (tid >> 1) & 7, v = tid & 1;
        float s = 0.f;
        for (int t = 0; t < 32; t++) s += ps[((r * 32 + t) * 8 + oz) * 2 + v];
        sc_part[oc0 + r * 8 + oz][tblk][v] = s;
    }
}

// ---------------- K2: base BN stats from 1024 partials ----------------
__global__ void k2_base_stats(const float* __restrict__ gam, const float* __restrict__ bet) {
    __shared__ float red[256];
    int c = blockIdx.x, tid = threadIdx.x;
    float s = 0.f, q = 0.f;
    for (int i = tid; i < 1024; i += 256) { s += sc_part[c][i][0]; q += sc_part[c][i][1]; }
    float sum = block_reduce(s, red, tid);
    float sq = block_reduce(q, red, tid);
    if (tid == 0) {
        float inv_n = 1.f / (float)(NB * HWSZ);
        float mean = sum * inv_n;
        float var = sq * inv_n - mean * mean;
        float inv = rsqrtf(var + BNEPS);
        float scl = gam[c] * inv;
        sc_scaleA[c] = scl;
        sc_shiftA[c] = bet[c] - mean * scl;
    }
}

// ---------------- K3: fold base BN into 1x1 conv weights ----------------
__global__ void k3_fold(const float* __restrict__ Wc, const float* __restrict__ bc,
                        const float* __restrict__ Wr, const float* __restrict__ br) {
    __shared__ float red[256];
    int o = blockIdx.x, ci = threadIdx.x;
    const float* Ws;
    float bs;
    int ol;
    if (o < NCLS) { Ws = Wc; ol = o; bs = bc[o]; }
    else { Ws = Wr; ol = o - NCLS; bs = br[ol]; }
    float w = Ws[ol * CIN + ci];
    sc_Wf[o * CIN + ci] = w * sc_scaleA[ci];
    float tot = block_reduce(w * sc_shiftA[ci], red, ci);
    if (ci == 0) sc_bf[o] = bs + tot;
}

// ---------------- K4m: merged 1x1 convs (cls+reg), fp16 reads, adjacent px ----------------
#define K4_SMEM (CIN * 56 * 4)
__global__ void __launch_bounds__(256) k4m() {
    extern __shared__ float swf[];
    int tid = threadIdx.x;
    for (int i = tid; i < CIN * 56; i += 256) {
        int c = i / 56, o = i - c * 56;
        swf[i] = (o < NTOT) ? sc_Wf[o * CIN + c] : 0.f;
    }
    __syncthreads();
    int pstart = blockIdx.x * 512;
    int n = pstart >> 14;
    int hw2 = (pstart & 16383) + 2 * tid;   // px at hw2, hw2+1 (adjacent)

    unsigned long long acc2[27][2];
#pragma unroll
    for (int op = 0; op < 27; op++) {
        unsigned long long b = pk2ab(sc_bf[2 * op], sc_bf[2 * op + 1]);
        acc2[op][0] = b;
        acc2[op][1] = b;
    }
    const __half* bpn = sc_base + (size_t)n * OCB * HWSZ + hw2;
#pragma unroll 1
    for (int c = 0; c < CIN; c += 8) {
        float2 f[8];
#pragma unroll
        for (int u = 0; u < 8; u++) {
            __half2 h = *(const __half2*)(bpn + (size_t)(c + u) * HWSZ);
            f[u] = __half22float2(h);
        }
#pragma unroll
        for (int u = 0; u < 8; u++) {
            unsigned long long p0 = pk2(f[u].x), p1 = pk2(f[u].y);
            const unsigned long long* wrow = (const unsigned long long*)(swf + (c + u) * 56);
#pragma unroll
            for (int op = 0; op < 27; op++) {
                unsigned long long w = wrow[op];
                fma2(acc2[op][0], w, p0);
                fma2(acc2[op][1], w, p1);
            }
        }
    }
#pragma unroll
    for (int op = 0; op < 27; op++) {
        float2 a = upk(acc2[op][0]);   // px0: (ch0, ch1)
        float2 b = upk(acc2[op][1]);   // px1: (ch0, ch1)
        int ch0 = 2 * op, ch1 = 2 * op + 1;
        if (ch0 < NCLS)
            *(float2*)(sc_cls + (size_t)(n * NCLS + ch0) * HWSZ + hw2) = make_float2(a.x, b.x);
        else
            *(float2*)(sc_reg + (size_t)(n * NREG + (ch0 - NCLS)) * HWSZ + hw2) = make_float2(a.x, b.x);
        if (ch1 < NCLS)
            *(float2*)(sc_cls + (size_t)(n * NCLS + ch1) * HWSZ + hw2) = make_float2(a.y, b.y);
        else
            *(float2*)(sc_reg + (size_t)(n * NREG + (ch1 - NCLS)) * HWSZ + hw2) = make_float2(a.y, b.y);
    }
}

// ---------------- K5: cls/reg BN stats ----------------
__global__ void k5_stats2(const float* __restrict__ gc, const float* __restrict__ bc,
                          const float* __restrict__ gr, const float* __restrict__ br) {
    __shared__ float red[256];
    int b = blockIdx.x, tid = threadIdx.x;
    const float* src;
    int nch, ch;
    float gam, bet;
    if (b < NCLS) { src = sc_cls; nch = NCLS; ch = b; gam = gc[ch]; bet = bc[ch]; }
    else { src = sc_reg; nch = NREG; ch = b - NCLS; gam = gr[ch]; bet = br[ch]; }
    float s = 0.f;
    for (int n = 0; n < NB; n++) {
        const float* p = &src[(size_t)(n * nch + ch) * HWSZ];
        for (int i = tid; i < HWSZ; i += 256) s += p[i];
    }
    float mean = block_reduce(s, red, tid) * (1.f / (NB * HWSZ));
    s = 0.f;
    for (int n = 0; n < NB; n++) {
        const float* p = &src[(size_t)(n * nch + ch) * HWSZ];
        for (int i = tid; i < HWSZ; i += 256) {
            float d = p[i] - mean;
            s += d * d;
        }
    }
    float var = block_reduce(s, red, tid) * (1.f / (NB * HWSZ));
    if (tid == 0) {
        float inv = rsqrtf(var + BNEPS);
        float scl = gam * inv;
        sc_s2[b] = scl;
        sc_h2[b] = bet - mean * scl;
    }
}

// ---------------- K6: softmax + anchor decode ----------------
__constant__ float c_wa[9] = {455.f, 911.f, 1823.f, 319.f, 639.f, 1279.f, 223.f, 447.f, 895.f};
__constant__ float c_ha[9] = {223.f, 447.f, 895.f, 319.f, 639.f, 1279.f, 447.f, 895.f, 1791.f};

__global__ void k6_decode(const int* __restrict__ imgsz, float* __restrict__ out) {
    int t = blockIdx.x * 256 + threadIdx.x;
    if (t >= NB * HWSZ) return;
    int n = t >> 14, hw = t & 16383;
    int hy = hw >> 7, wx = hw & 127;
    float lim = 2048.f;
    if (imgsz) {
        int iv = *imgsz;
        lim = (iv > 0 && iv < (1 << 24)) ? (float)iv : __int_as_float(iv);
    }
    float cls[NCLS], rg[NREG];
#pragma unroll
    for (int o = 0; o < NCLS; o++)
        cls[o] = sc_cls[(size_t)(n * NCLS + o) * HWSZ + hw] * sc_s2[o] + sc_h2[o];
#pragma unroll
    for (int o = 0; o < NREG; o++)
        rg[o] = sc_reg[(size_t)(n * NREG + o) * HWSZ + hw] * sc_s2[NCLS + o] + sc_h2[NCLS + o];

    const size_t K = (size_t)HWSZ * 9;
    float* fg = out;
    float* ts = out + (size_t)NB * K;
    float* ro = ts + (size_t)NB * K * 4;
    size_t kb = (size_t)n * K + (size_t)hw * 9;

    float cxa = 19.5f + 16.f * (float)wx;
    float cya = 19.5f + 16.f * (float)hy;
#pragma unroll
    for (int a = 0; a < 9; a++) {
        float wa = c_wa[a], ha = c_ha[a];
        float x1 = fminf(fmaxf(rg[a * 4 + 0] + (cxa - 0.5f * wa), 0.f), lim);
        float y1 = fminf(fmaxf(rg[a * 4 + 1] + (cya - 0.5f * ha), 0.f), lim);
        float x2 = fminf(fmaxf(rg[a * 4 + 2] + (cxa + 0.5f * wa), 0.f), lim);
        float y2 = fminf(fmaxf(rg[a * 4 + 3] + (cya + 0.5f * ha), 0.f), lim);
        float w = x2 - x1, h = y2 - y1;
        float cx = x1 + 0.5f * w, cy = y1 + 0.5f * h;
        float s0 = cls[a * 2], s1 = cls[a * 2 + 1];
        fg[kb + a] = 1.f / (1.f + expf(s0 - s1));
        size_t o4 = (kb + a) * 4;
        ts[o4 + 0] = (cx - cxa) / wa;
        ts[o4 + 1] = (cy - cya) / ha;
        ts[o4 + 2] = logf(fmaxf(w / wa, 1e-30f));
        ts[o4 + 3] = logf(fmaxf(h / ha, 1e-30f));
        ro[o4 + 0] = cx;
        ro[o4 + 1] = cy;
        ro[o4 + 2] = w;
        ro[o4 + 3] = h;
    }
}

// ---------------- launch ----------------
extern "C" void kernel_launch(void* const* d_in, const int* in_sizes, int n_in,
                              void* d_out, int out_size) {
    const float* x   = (const float*)d_in[0];
    const float* Wb  = (const float*)d_in[1];
    const float* bb  = (const float*)d_in[2];
    const float* gb  = (const float*)d_in[3];
    const float* beb = (const float*)d_in[4];
    const float* Wc  = (const float*)d_in[5];
    const float* bc  = (const float*)d_in[6];
    const float* gc  = (const float*)d_in[7];
    const float* bec = (const float*)d_in[8];
    const float* Wr  = (const float*)d_in[9];
    const float* br  = (const float*)d_in[10];
    const float* gr  = (const float*)d_in[11];
    const float* ber = (const float*)d_in[12];
    const int* imgsz = (n_in > 13) ? (const int*)d_in[13] : nullptr;
    float* out = (float*)d_out;

    static int smem_set = 0;
    if (!smem_set) {
        cudaFuncSetAttribute(kG, cudaFuncAttributeMaxDynamicSharedMemorySize, G_SMEM);
        cudaFuncSetAttribute(kV, cudaFuncAttributeMaxDynamicSharedMemorySize, KV_SMEM);
        cudaFuncSetAttribute(k4m, cudaFuncAttributeMaxDynamicSharedMemorySize, K4_SMEM);
        smem_set = 1;
    }

    kU<<<256, 256>>>(Wb);                            // launch 0
    kV<<<dim3(16, 64, NB), 256, KV_SMEM>>>(x);       // launch 1
    kdummy<<<1, 32>>>();                             // launch 2 (aligns ncu capture onto kG)
    kG<<<dim3(4, 1024), 256, G_SMEM>>>(bb);          // launch 3 <- profiled

    k2_base_stats<<<OCB, 256>>>(gb, beb);
    k3_fold<<<NTOT, 256>>>(Wc, bc, Wr, br);
    k4m<<<NB * HWSZ / 512, 256, K4_SMEM>>>();
    k5_stats2<<<NTOT, 256>>>(gc, bec, gr, ber);
    k6_decode<<<NB * HWSZ / 256, 256>>>(imgsz, out);
}